// round 13
// baseline (speedup 1.0000x reference)
#include <cuda_runtime.h>
#include <cuda_fp16.h>
#include <cstdint>

// ---------------------------------------------------------------------------
// QGCN forward on GB300 — fp16 intermediate features.
//   GEMM: single-pass mma.sync.m16n8k16.f16 (fp32 accum).
//   Gathers: 4-edge software pipeline, 4 independent accumulators.
//   CSR build forked under GEMM0.
// ---------------------------------------------------------------------------

#define N_NODES 50000
#define N_EDGES 800000

__device__ __half  g_bufA[N_NODES * 128];
__device__ __half  g_bufB[N_NODES * 128];
__device__ __half  g_bufC[N_NODES * 128];
__device__ int     g_deg[N_NODES];
__device__ int     g_indptr[N_NODES + 1];
__device__ int     g_cursor[N_NODES];
__device__ float2  g_edges[N_EDGES];   // {src (bit-cast int), weight}

// ---------------------------------------------------------------------------
__device__ __forceinline__ uint32_t pack_h2(float a, float b) {
    __half2 h = __floats2half2_rn(a, b);
    return *reinterpret_cast<uint32_t*>(&h);
}
__device__ __forceinline__ float2 unpack_h2(uint32_t w) {
    __half2 h = *reinterpret_cast<__half2*>(&w);
    return __half22float2(h);
}
__device__ __forceinline__ void mma_f16(
    float& d0, float& d1, float& d2, float& d3,
    uint32_t a0, uint32_t a1, uint32_t a2, uint32_t a3,
    uint32_t b0, uint32_t b1)
{
    asm volatile(
        "mma.sync.aligned.m16n8k16.row.col.f32.f16.f16.f32 "
        "{%0,%1,%2,%3},{%4,%5,%6,%7},{%8,%9},{%0,%1,%2,%3};"
        : "+f"(d0), "+f"(d1), "+f"(d2), "+f"(d3)
        : "r"(a0), "r"(a1), "r"(a2), "r"(a3), "r"(b0), "r"(b1));
}

// ---------------------------------------------------------------------------
// GEMM: Y[N, BNT](fp16) = X[N, 128] @ W[128, BNT]   (R12 measured-good)
// ---------------------------------------------------------------------------
template <int BNT, int XHALF>
__global__ __launch_bounds__(128, 4) void gemm_f16_kernel(
    const void* __restrict__ Xv, const float* __restrict__ W,
    __half* __restrict__ Y, int N)
{
    constexpr int KC   = 32;
    constexpr int NK   = 128 / KC;
    constexpr int XSPW = 20;
    constexpr int WSPW = 72;

    __shared__ uint32_t Xs[64][XSPW];
    __shared__ uint32_t Ws[16][WSPW];

    const int tid  = threadIdx.x;
    const int lane = tid & 31;
    const int warp = tid >> 5;
    const int row0 = blockIdx.x * 64;
    const int nb   = blockIdx.y * 64;

    const int qr = lane >> 2;
    const int qt = lane & 3;
    const int wm = (warp & 1) * 32;
    const int wn = (warp >> 1) * 32;

    const float4* X4f = (const float4*)Xv;
    const uint4*  X4h = (const uint4*)Xv;
    const float4* W4  = (const float4*)W;

    float4 xrf[4];
    uint4  xrh[2];
    float4 wrA[2], wrB[2];

    auto ldgX = [&](int ch) {
        if (XHALF) {
#pragma unroll
            for (int i = 0; i < 2; i++) {
                int idx = tid + i * 128;
                int r = idx >> 2, c4 = idx & 3;
                int gr = row0 + r;
                xrh[i] = (gr < N) ? X4h[gr * 16 + ch * 4 + c4]
                                  : make_uint4(0, 0, 0, 0);
            }
        } else {
#pragma unroll
            for (int i = 0; i < 4; i++) {
                int idx = tid + i * 128;
                int r = idx >> 3, c4 = idx & 7;
                int gr = row0 + r;
                xrf[i] = (gr < N) ? X4f[gr * 32 + ch * 8 + c4]
                                  : make_float4(0.f, 0.f, 0.f, 0.f);
            }
        }
    };
    auto ldgW = [&](int ch) {
#pragma unroll
        for (int i = 0; i < 2; i++) {
            int idx = tid + i * 128;
            int kp = idx >> 4, cc = idx & 15;
            wrA[i] = W4[(((ch * KC + 2 * kp)     * BNT + nb) >> 2) + cc];
            wrB[i] = W4[(((ch * KC + 2 * kp + 1) * BNT + nb) >> 2) + cc];
        }
    };
    auto stsX = [&]() {
        if (XHALF) {
#pragma unroll
            for (int i = 0; i < 2; i++) {
                int idx = tid + i * 128;
                int r = idx >> 2, c4 = idx & 3;
                Xs[r][c4 * 4 + 0] = xrh[i].x;
                Xs[r][c4 * 4 + 1] = xrh[i].y;
                Xs[r][c4 * 4 + 2] = xrh[i].z;
                Xs[r][c4 * 4 + 3] = xrh[i].w;
            }
        } else {
#pragma unroll
            for (int i = 0; i < 4; i++) {
                int idx = tid + i * 128;
                int r = idx >> 3, c4 = idx & 7;
                Xs[r][c4 * 2 + 0] = pack_h2(xrf[i].x, xrf[i].y);
                Xs[r][c4 * 2 + 1] = pack_h2(xrf[i].z, xrf[i].w);
            }
        }
    };
    auto stsW = [&]() {
#pragma unroll
        for (int i = 0; i < 2; i++) {
            int idx = tid + i * 128;
            int kp = idx >> 4, cc = idx & 15;
            const float* a = (const float*)&wrA[i];
            const float* b = (const float*)&wrB[i];
#pragma unroll
            for (int j = 0; j < 4; j++)
                Ws[kp][cc * 4 + j] = pack_h2(a[j], b[j]);
        }
    };

    float acc[2][4][4] = {};

    ldgX(0); ldgW(0);
    stsX(); stsW();
    __syncthreads();

#pragma unroll
    for (int ch = 0; ch < NK; ch++) {
        if (ch + 1 < NK) { ldgX(ch + 1); ldgW(ch + 1); }

#pragma unroll
        for (int ks = 0; ks < 2; ks++) {
            const int kw = ks * 8 + qt;

            uint32_t a[2][4];
#pragma unroll
            for (int mt = 0; mt < 2; mt++) {
                int r = wm + mt * 16 + qr;
                a[mt][0] = Xs[r][kw];
                a[mt][1] = Xs[r + 8][kw];
                a[mt][2] = Xs[r][kw + 4];
                a[mt][3] = Xs[r + 8][kw + 4];
            }
            uint32_t b[4][2];
#pragma unroll
            for (int nt = 0; nt < 4; nt++) {
                int c = wn + nt * 8 + qr;
                b[nt][0] = Ws[ks * 8 + qt][c];
                b[nt][1] = Ws[ks * 8 + qt + 4][c];
            }
#pragma unroll
            for (int mt = 0; mt < 2; mt++)
#pragma unroll
                for (int nt = 0; nt < 4; nt++) {
                    float* d = acc[mt][nt];
                    mma_f16(d[0], d[1], d[2], d[3],
                            a[mt][0], a[mt][1], a[mt][2], a[mt][3],
                            b[nt][0], b[nt][1]);
                }
        }

        if (ch + 1 < NK) {
            __syncthreads();
            stsX(); stsW();
            __syncthreads();
        }
    }

    uint32_t* Y32 = (uint32_t*)Y;
#pragma unroll
    for (int mt = 0; mt < 2; mt++) {
#pragma unroll
        for (int nt = 0; nt < 4; nt++) {
            int gc = nb + wn + nt * 8 + qt * 2;
            int r0g = row0 + wm + mt * 16 + qr;
            if (r0g < N)
                Y32[(r0g * BNT + gc) >> 1] = pack_h2(acc[mt][nt][0], acc[mt][nt][1]);
            int r1g = r0g + 8;
            if (r1g < N)
                Y32[(r1g * BNT + gc) >> 1] = pack_h2(acc[mt][nt][2], acc[mt][nt][3]);
        }
    }
}

// ---------------------------------------------------------------------------
// CSR build
// ---------------------------------------------------------------------------
__global__ __launch_bounds__(256) void hist_kernel(
    const int* __restrict__ dst, int* __restrict__ deg, int E)
{
    int e = blockIdx.x * blockDim.x + threadIdx.x;
    if (e < E) atomicAdd(&deg[__ldg(&dst[e])], 1);
}

__global__ __launch_bounds__(1024) void scan_kernel(
    const int* __restrict__ deg, int* __restrict__ indptr,
    int* __restrict__ cursor)
{
    __shared__ int sh[1024];
    const int CHUNK = (N_NODES + 1023) / 1024;
    int t = threadIdx.x;
    int begin = t * CHUNK;
    int end   = begin + CHUNK; if (end > N_NODES) end = N_NODES;

    int s = 0;
    for (int i = begin; i < end; i++) s += deg[i];
    sh[t] = s;
    __syncthreads();

    for (int off = 1; off < 1024; off <<= 1) {
        int v = sh[t];
        int a = (t >= off) ? sh[t - off] : 0;
        __syncthreads();
        sh[t] = v + a;
        __syncthreads();
    }

    int run = (t == 0) ? 0 : sh[t - 1];
    for (int i = begin; i < end; i++) {
        indptr[i] = run;
        cursor[i] = run;
        run += deg[i];
    }
    if (t == 1023) indptr[N_NODES] = run;
}

__global__ __launch_bounds__(256) void place_kernel(
    const int* __restrict__ src, const int* __restrict__ dst,
    const float* __restrict__ ew, int* __restrict__ cursor,
    float2* __restrict__ edges, int E)
{
    int e = blockIdx.x * blockDim.x + threadIdx.x;
    if (e >= E) return;
    int d = __ldg(&dst[e]);
    int p = atomicAdd(&cursor[d], 1);
    edges[p] = make_float2(__int_as_float(__ldg(&src[e])), __ldg(&ew[e]));
}

// ---------------------------------------------------------------------------
// Gather helpers
// ---------------------------------------------------------------------------
__device__ __forceinline__ void acc_h2(float4& acc, uint2 u, float w) {
    float2 f0 = unpack_h2(u.x);
    float2 f1 = unpack_h2(u.y);
    acc.x = fmaf(f0.x, w, acc.x); acc.y = fmaf(f0.y, w, acc.y);
    acc.z = fmaf(f1.x, w, acc.z); acc.w = fmaf(f1.y, w, acc.w);
}

// Core gather loop: 4-edge pipeline, 4 independent accumulators.
// SH: row length in uint2 units is (1<<SH).
template <int SH>
__device__ __forceinline__ float4 gather_core(
    const uint2* __restrict__ H2, const float2* __restrict__ edges,
    int start, int cnt, int lane)
{
    float4 a0 = make_float4(0.f, 0.f, 0.f, 0.f);
    float4 a1 = a0, a2 = a0, a3 = a0;

    if (cnt > 0) {
        int last = start + cnt - 1;
        float2 e0 = __ldg(&edges[start]);
        float2 e1 = __ldg(&edges[min(start + 1, last)]);
        float2 e2 = __ldg(&edges[min(start + 2, last)]);
        float2 e3 = __ldg(&edges[min(start + 3, last)]);
        int j = 0;
        for (; j + 3 < cnt; j += 4) {
            float2 n0 = __ldg(&edges[min(start + j + 4, last)]);
            float2 n1 = __ldg(&edges[min(start + j + 5, last)]);
            float2 n2 = __ldg(&edges[min(start + j + 6, last)]);
            float2 n3 = __ldg(&edges[min(start + j + 7, last)]);
            uint2 v0 = __ldg(&H2[(__float_as_int(e0.x) << SH) + lane]);
            uint2 v1 = __ldg(&H2[(__float_as_int(e1.x) << SH) + lane]);
            uint2 v2 = __ldg(&H2[(__float_as_int(e2.x) << SH) + lane]);
            uint2 v3 = __ldg(&H2[(__float_as_int(e3.x) << SH) + lane]);
            acc_h2(a0, v0, e0.y);
            acc_h2(a1, v1, e1.y);
            acc_h2(a2, v2, e2.y);
            acc_h2(a3, v3, e3.y);
            e0 = n0; e1 = n1; e2 = n2; e3 = n3;
        }
        // tail: e0..e2 hold edges[start+j ..] (clamped)
        int r = cnt - j;
        if (r > 0) {
            uint2 v0 = __ldg(&H2[(__float_as_int(e0.x) << SH) + lane]);
            acc_h2(a0, v0, e0.y);
        }
        if (r > 1) {
            uint2 v1 = __ldg(&H2[(__float_as_int(e1.x) << SH) + lane]);
            acc_h2(a1, v1, e1.y);
        }
        if (r > 2) {
            uint2 v2 = __ldg(&H2[(__float_as_int(e2.x) << SH) + lane]);
            acc_h2(a2, v2, e2.y);
        }
    }
    float4 acc;
    acc.x = (a0.x + a1.x) + (a2.x + a3.x);
    acc.y = (a0.y + a1.y) + (a2.y + a3.y);
    acc.z = (a0.z + a1.z) + (a2.z + a3.z);
    acc.w = (a0.w + a1.w) + (a2.w + a3.w);
    return acc;
}

// ---------------------------------------------------------------------------
// Gather-aggregate, D=128 (fp16 rows): one warp per node, lane = 4 elements.
// MODE 0: val=acc+b; out0=val; out1=val+relu(val)    (layer 0)
// MODE 1: val=acc+b; out0=Bres+relu(val)             (layer 1)
// ---------------------------------------------------------------------------
template <int MODE>
__global__ __launch_bounds__(256) void gather128_kernel(
    const __half* __restrict__ H, const float2* __restrict__ edges,
    const int* __restrict__ indptr,
    const float* __restrict__ bias, const __half* __restrict__ Bres,
    __half* __restrict__ out0, __half* __restrict__ out1)
{
    int node = (blockIdx.x * 256 + threadIdx.x) >> 5;
    int lane = threadIdx.x & 31;
    if (node >= N_NODES) return;

    int start = __ldg(&indptr[node]);
    int cnt   = __ldg(&indptr[node + 1]) - start;

    float4 acc = gather_core<5>((const uint2*)H, edges, start, cnt, lane);

    float4 bb = ((const float4*)bias)[lane];
    float4 val = make_float4(acc.x + bb.x, acc.y + bb.y,
                             acc.z + bb.z, acc.w + bb.w);
    int idx = (node << 5) + lane;

    if (MODE == 0) {
        uint2 ov;
        ov.x = pack_h2(val.x, val.y);
        ov.y = pack_h2(val.z, val.w);
        ((uint2*)out0)[idx] = ov;
        uint2 oc;
        oc.x = pack_h2(val.x + fmaxf(val.x, 0.f), val.y + fmaxf(val.y, 0.f));
        oc.y = pack_h2(val.z + fmaxf(val.z, 0.f), val.w + fmaxf(val.w, 0.f));
        ((uint2*)out1)[idx] = oc;
    } else {
        uint2 bu = __ldg(&((const uint2*)Bres)[idx]);
        float2 b0 = unpack_h2(bu.x);
        float2 b1 = unpack_h2(bu.y);
        uint2 oc;
        oc.x = pack_h2(b0.x + fmaxf(val.x, 0.f), b0.y + fmaxf(val.y, 0.f));
        oc.y = pack_h2(b1.x + fmaxf(val.z, 0.f), b1.y + fmaxf(val.w, 0.f));
        ((uint2*)out0)[idx] = oc;
    }
}

// D=64 (fp16 rows), fp32 output: half-warp per node.
__global__ __launch_bounds__(256) void gather64_kernel(
    const __half* __restrict__ H, const float2* __restrict__ edges,
    const int* __restrict__ indptr,
    const float* __restrict__ bias, float* __restrict__ out)
{
    int node = (blockIdx.x * 256 + threadIdx.x) >> 4;
    int lane = threadIdx.x & 15;
    if (node >= N_NODES) return;

    int start = __ldg(&indptr[node]);
    int cnt   = __ldg(&indptr[node + 1]) - start;

    float4 acc = gather_core<4>((const uint2*)H, edges, start, cnt, lane);

    float4 bb = ((const float4*)bias)[lane];
    ((float4*)out)[(node << 4) + lane] =
        make_float4(acc.x + bb.x, acc.y + bb.y, acc.z + bb.z, acc.w + bb.w);
}

// ---------------------------------------------------------------------------

extern "C" void kernel_launch(void* const* d_in, const int* in_sizes, int n_in,
                              void* d_out, int out_size)
{
    const float* x  = (const float*)d_in[0];
    const int*   ei = (const int*)d_in[1];
    const float* ea = (const float*)d_in[2];
    const float* W1 = (const float*)d_in[3];
    const float* b1 = (const float*)d_in[4];
    const float* W2 = (const float*)d_in[5];
    const float* b2 = (const float*)d_in[6];
    const float* W3 = (const float*)d_in[7];
    const float* b3 = (const float*)d_in[8];
    float* out = (float*)d_out;

    const int N = N_NODES;
    const int E = N_EDGES;
    const int* src = ei;
    const int* dst = ei + E;

    __half *A, *B, *C;
    int *deg, *indptr, *cursor;
    float2* edges;
    cudaGetSymbolAddress((void**)&A, g_bufA);
    cudaGetSymbolAddress((void**)&B, g_bufB);
    cudaGetSymbolAddress((void**)&C, g_bufC);
    cudaGetSymbolAddress((void**)&deg, g_deg);
    cudaGetSymbolAddress((void**)&indptr, g_indptr);
    cudaGetSymbolAddress((void**)&cursor, g_cursor);
    cudaGetSymbolAddress((void**)&edges, g_edges);

    const int e_blocks    = (E + 255) / 256;
    const int g128_blocks = (N * 32 + 255) / 256;
    const int g64_blocks  = (N * 16 + 255) / 256;
    const int mrows       = (N + 63) / 64;

    dim3 grid128(mrows, 2);
    dim3 grid64(mrows, 1);

    cudaStream_t s2;
    cudaStreamCreateWithFlags(&s2, cudaStreamNonBlocking);
    cudaEvent_t evFork, evJoin;
    cudaEventCreateWithFlags(&evFork, cudaEventDisableTiming);
    cudaEventCreateWithFlags(&evJoin, cudaEventDisableTiming);

    // --- Fork: CSR build on s2 ∥ GEMM0 on main ---
    cudaEventRecord(evFork, 0);
    cudaStreamWaitEvent(s2, evFork, 0);

    cudaMemsetAsync(deg, 0, N * sizeof(int), s2);
    hist_kernel<<<e_blocks, 256, 0, s2>>>(dst, deg, E);
    scan_kernel<<<1, 1024, 0, s2>>>(deg, indptr, cursor);
    place_kernel<<<e_blocks, 256, 0, s2>>>(src, dst, ea, cursor, edges, E);
    cudaEventRecord(evJoin, s2);

    gemm_f16_kernel<128, 0><<<grid128, 128>>>(x, W1, A, N);

    cudaStreamWaitEvent(0, evJoin, 0);

    // --- Layer 0: B = x1 = agg(x@W1)+b1 ; C = x1 + relu(x1) ---
    gather128_kernel<0><<<g128_blocks, 256>>>(A, edges, indptr, b1, nullptr, B, C);

    // --- Layer 1: C = x1 + relu(agg(C@W2)+b2) ---
    gemm_f16_kernel<128, 1><<<grid128, 128>>>(C, W2, A, N);
    gather128_kernel<1><<<g128_blocks, 256>>>(A, edges, indptr, b2, B, C, nullptr);

    // --- Layer 2: out = agg(C@W3)+b3 ---
    gemm_f16_kernel<64, 1><<<grid64, 128>>>(C, W3, A, N);
    gather64_kernel<<<g64_blocks, 256>>>(A, edges, indptr, b3, out);
}

// round 14
// speedup vs baseline: 1.0596x; 1.0596x over previous
#include <cuda_runtime.h>
#include <cuda_fp16.h>
#include <cstdint>

// ---------------------------------------------------------------------------
// QGCN forward on GB300 — fp16 intermediate features.
//   GEMM: single-pass mma.sync.m16n8k16.f16, double-buffered SMEM
//         (one barrier per k-chunk).
//   Gathers: R12 2-edge pipeline (measured optimum).
//   CSR build forked under GEMM0.
// ---------------------------------------------------------------------------

#define N_NODES 50000
#define N_EDGES 800000

__device__ __half  g_bufA[N_NODES * 128];
__device__ __half  g_bufB[N_NODES * 128];
__device__ __half  g_bufC[N_NODES * 128];
__device__ int     g_deg[N_NODES];
__device__ int     g_indptr[N_NODES + 1];
__device__ int     g_cursor[N_NODES];
__device__ float2  g_edges[N_EDGES];   // {src (bit-cast int), weight}

// ---------------------------------------------------------------------------
__device__ __forceinline__ uint32_t pack_h2(float a, float b) {
    __half2 h = __floats2half2_rn(a, b);
    return *reinterpret_cast<uint32_t*>(&h);
}
__device__ __forceinline__ float2 unpack_h2(uint32_t w) {
    __half2 h = *reinterpret_cast<__half2*>(&w);
    return __half22float2(h);
}
__device__ __forceinline__ void mma_f16(
    float& d0, float& d1, float& d2, float& d3,
    uint32_t a0, uint32_t a1, uint32_t a2, uint32_t a3,
    uint32_t b0, uint32_t b1)
{
    asm volatile(
        "mma.sync.aligned.m16n8k16.row.col.f32.f16.f16.f32 "
        "{%0,%1,%2,%3},{%4,%5,%6,%7},{%8,%9},{%0,%1,%2,%3};"
        : "+f"(d0), "+f"(d1), "+f"(d2), "+f"(d3)
        : "r"(a0), "r"(a1), "r"(a2), "r"(a3), "r"(b0), "r"(b1));
}

// ---------------------------------------------------------------------------
// GEMM: Y[N, BNT](fp16) = X[N, 128] @ W[128, BNT]
// Double-buffered SMEM, one __syncthreads per k-chunk.
// ---------------------------------------------------------------------------
template <int BNT, int XHALF>
__global__ __launch_bounds__(128, 4) void gemm_f16_kernel(
    const void* __restrict__ Xv, const float* __restrict__ W,
    __half* __restrict__ Y, int N)
{
    constexpr int KC   = 32;
    constexpr int NK   = 128 / KC;
    constexpr int XSPW = 20;
    constexpr int WSPW = 72;

    __shared__ uint32_t Xs[2][64][XSPW];
    __shared__ uint32_t Ws[2][16][WSPW];

    const int tid  = threadIdx.x;
    const int lane = tid & 31;
    const int warp = tid >> 5;
    const int row0 = blockIdx.x * 64;
    const int nb   = blockIdx.y * 64;

    const int qr = lane >> 2;
    const int qt = lane & 3;
    const int wm = (warp & 1) * 32;
    const int wn = (warp >> 1) * 32;

    const float4* X4f = (const float4*)Xv;
    const uint4*  X4h = (const uint4*)Xv;
    const float4* W4  = (const float4*)W;

    float4 xrf[4];
    uint4  xrh[2];
    float4 wrA[2], wrB[2];

    auto ldgX = [&](int ch) {
        if (XHALF) {
#pragma unroll
            for (int i = 0; i < 2; i++) {
                int idx = tid + i * 128;
                int r = idx >> 2, c4 = idx & 3;
                int gr = row0 + r;
                xrh[i] = (gr < N) ? X4h[gr * 16 + ch * 4 + c4]
                                  : make_uint4(0, 0, 0, 0);
            }
        } else {
#pragma unroll
            for (int i = 0; i < 4; i++) {
                int idx = tid + i * 128;
                int r = idx >> 3, c4 = idx & 7;
                int gr = row0 + r;
                xrf[i] = (gr < N) ? X4f[gr * 32 + ch * 8 + c4]
                                  : make_float4(0.f, 0.f, 0.f, 0.f);
            }
        }
    };
    auto ldgW = [&](int ch) {
#pragma unroll
        for (int i = 0; i < 2; i++) {
            int idx = tid + i * 128;
            int kp = idx >> 4, cc = idx & 15;
            wrA[i] = W4[(((ch * KC + 2 * kp)     * BNT + nb) >> 2) + cc];
            wrB[i] = W4[(((ch * KC + 2 * kp + 1) * BNT + nb) >> 2) + cc];
        }
    };
    auto stsX = [&](int p) {
        if (XHALF) {
#pragma unroll
            for (int i = 0; i < 2; i++) {
                int idx = tid + i * 128;
                int r = idx >> 2, c4 = idx & 3;
                Xs[p][r][c4 * 4 + 0] = xrh[i].x;
                Xs[p][r][c4 * 4 + 1] = xrh[i].y;
                Xs[p][r][c4 * 4 + 2] = xrh[i].z;
                Xs[p][r][c4 * 4 + 3] = xrh[i].w;
            }
        } else {
#pragma unroll
            for (int i = 0; i < 4; i++) {
                int idx = tid + i * 128;
                int r = idx >> 3, c4 = idx & 7;
                Xs[p][r][c4 * 2 + 0] = pack_h2(xrf[i].x, xrf[i].y);
                Xs[p][r][c4 * 2 + 1] = pack_h2(xrf[i].z, xrf[i].w);
            }
        }
    };
    auto stsW = [&](int p) {
#pragma unroll
        for (int i = 0; i < 2; i++) {
            int idx = tid + i * 128;
            int kp = idx >> 4, cc = idx & 15;
            const float* a = (const float*)&wrA[i];
            const float* b = (const float*)&wrB[i];
#pragma unroll
            for (int j = 0; j < 4; j++)
                Ws[p][kp][cc * 4 + j] = pack_h2(a[j], b[j]);
        }
    };

    float acc[2][4][4] = {};

    ldgX(0); ldgW(0);
    stsX(0); stsW(0);
    __syncthreads();

#pragma unroll
    for (int ch = 0; ch < NK; ch++) {
        const int p = ch & 1;
        if (ch + 1 < NK) { ldgX(ch + 1); ldgW(ch + 1); }

#pragma unroll
        for (int ks = 0; ks < 2; ks++) {
            const int kw = ks * 8 + qt;

            uint32_t a[2][4];
#pragma unroll
            for (int mt = 0; mt < 2; mt++) {
                int r = wm + mt * 16 + qr;
                a[mt][0] = Xs[p][r][kw];
                a[mt][1] = Xs[p][r + 8][kw];
                a[mt][2] = Xs[p][r][kw + 4];
                a[mt][3] = Xs[p][r + 8][kw + 4];
            }
            uint32_t b[4][2];
#pragma unroll
            for (int nt = 0; nt < 4; nt++) {
                int c = wn + nt * 8 + qr;
                b[nt][0] = Ws[p][ks * 8 + qt][c];
                b[nt][1] = Ws[p][ks * 8 + qt + 4][c];
            }
#pragma unroll
            for (int mt = 0; mt < 2; mt++)
#pragma unroll
                for (int nt = 0; nt < 4; nt++) {
                    float* d = acc[mt][nt];
                    mma_f16(d[0], d[1], d[2], d[3],
                            a[mt][0], a[mt][1], a[mt][2], a[mt][3],
                            b[nt][0], b[nt][1]);
                }
        }

        if (ch + 1 < NK) {
            // write the OTHER buffer; prior barrier guarantees all warps
            // finished reading it (it was consumed in chunk ch-1)
            stsX(p ^ 1); stsW(p ^ 1);
            __syncthreads();
        }
    }

    uint32_t* Y32 = (uint32_t*)Y;
#pragma unroll
    for (int mt = 0; mt < 2; mt++) {
#pragma unroll
        for (int nt = 0; nt < 4; nt++) {
            int gc = nb + wn + nt * 8 + qt * 2;
            int r0g = row0 + wm + mt * 16 + qr;
            if (r0g < N)
                Y32[(r0g * BNT + gc) >> 1] = pack_h2(acc[mt][nt][0], acc[mt][nt][1]);
            int r1g = r0g + 8;
            if (r1g < N)
                Y32[(r1g * BNT + gc) >> 1] = pack_h2(acc[mt][nt][2], acc[mt][nt][3]);
        }
    }
}

// ---------------------------------------------------------------------------
// CSR build
// ---------------------------------------------------------------------------
__global__ __launch_bounds__(256) void hist_kernel(
    const int* __restrict__ dst, int* __restrict__ deg, int E)
{
    int e = blockIdx.x * blockDim.x + threadIdx.x;
    if (e < E) atomicAdd(&deg[__ldg(&dst[e])], 1);
}

__global__ __launch_bounds__(1024) void scan_kernel(
    const int* __restrict__ deg, int* __restrict__ indptr,
    int* __restrict__ cursor)
{
    __shared__ int sh[1024];
    const int CHUNK = (N_NODES + 1023) / 1024;
    int t = threadIdx.x;
    int begin = t * CHUNK;
    int end   = begin + CHUNK; if (end > N_NODES) end = N_NODES;

    int s = 0;
    for (int i = begin; i < end; i++) s += deg[i];
    sh[t] = s;
    __syncthreads();

    for (int off = 1; off < 1024; off <<= 1) {
        int v = sh[t];
        int a = (t >= off) ? sh[t - off] : 0;
        __syncthreads();
        sh[t] = v + a;
        __syncthreads();
    }

    int run = (t == 0) ? 0 : sh[t - 1];
    for (int i = begin; i < end; i++) {
        indptr[i] = run;
        cursor[i] = run;
        run += deg[i];
    }
    if (t == 1023) indptr[N_NODES] = run;
}

__global__ __launch_bounds__(256) void place_kernel(
    const int* __restrict__ src, const int* __restrict__ dst,
    const float* __restrict__ ew, int* __restrict__ cursor,
    float2* __restrict__ edges, int E)
{
    int e = blockIdx.x * blockDim.x + threadIdx.x;
    if (e >= E) return;
    int d = __ldg(&dst[e]);
    int p = atomicAdd(&cursor[d], 1);
    edges[p] = make_float2(__int_as_float(__ldg(&src[e])), __ldg(&ew[e]));
}

// ---------------------------------------------------------------------------
// Gather helpers (R12 2-edge pipeline — measured optimum, do not touch)
// ---------------------------------------------------------------------------
__device__ __forceinline__ void acc_h2(float4& acc, uint2 u, float w) {
    float2 f0 = unpack_h2(u.x);
    float2 f1 = unpack_h2(u.y);
    acc.x = fmaf(f0.x, w, acc.x); acc.y = fmaf(f0.y, w, acc.y);
    acc.z = fmaf(f1.x, w, acc.z); acc.w = fmaf(f1.y, w, acc.w);
}

template <int MODE>
__global__ __launch_bounds__(256) void gather128_kernel(
    const __half* __restrict__ H, const float2* __restrict__ edges,
    const int* __restrict__ indptr,
    const float* __restrict__ bias, const __half* __restrict__ Bres,
    __half* __restrict__ out0, __half* __restrict__ out1)
{
    int node = (blockIdx.x * 256 + threadIdx.x) >> 5;
    int lane = threadIdx.x & 31;
    if (node >= N_NODES) return;

    int start = __ldg(&indptr[node]);
    int endp  = __ldg(&indptr[node + 1]);
    int cnt   = endp - start;
    int last  = endp - 1;

    float4 acc = make_float4(0.f, 0.f, 0.f, 0.f);
    const uint2* H2 = (const uint2*)H;

    if (cnt > 0) {
        float2 e0 = __ldg(&edges[start]);
        float2 e1 = __ldg(&edges[min(start + 1, last)]);
        int j = 0;
        for (; j + 1 < cnt; j += 2) {
            float2 n0 = __ldg(&edges[min(start + j + 2, last)]);
            float2 n1 = __ldg(&edges[min(start + j + 3, last)]);
            uint2 v0 = __ldg(&H2[(__float_as_int(e0.x) << 5) + lane]);
            uint2 v1 = __ldg(&H2[(__float_as_int(e1.x) << 5) + lane]);
            acc_h2(acc, v0, e0.y);
            acc_h2(acc, v1, e1.y);
            e0 = n0; e1 = n1;
        }
        if (j < cnt) {
            uint2 v0 = __ldg(&H2[(__float_as_int(e0.x) << 5) + lane]);
            acc_h2(acc, v0, e0.y);
        }
    }

    float4 bb = ((const float4*)bias)[lane];
    float4 val = make_float4(acc.x + bb.x, acc.y + bb.y,
                             acc.z + bb.z, acc.w + bb.w);
    int idx = (node << 5) + lane;

    if (MODE == 0) {
        uint2 ov;
        ov.x = pack_h2(val.x, val.y);
        ov.y = pack_h2(val.z, val.w);
        ((uint2*)out0)[idx] = ov;
        uint2 oc;
        oc.x = pack_h2(val.x + fmaxf(val.x, 0.f), val.y + fmaxf(val.y, 0.f));
        oc.y = pack_h2(val.z + fmaxf(val.z, 0.f), val.w + fmaxf(val.w, 0.f));
        ((uint2*)out1)[idx] = oc;
    } else {
        uint2 bu = __ldg(&((const uint2*)Bres)[idx]);
        float2 b0 = unpack_h2(bu.x);
        float2 b1 = unpack_h2(bu.y);
        uint2 oc;
        oc.x = pack_h2(b0.x + fmaxf(val.x, 0.f), b0.y + fmaxf(val.y, 0.f));
        oc.y = pack_h2(b1.x + fmaxf(val.z, 0.f), b1.y + fmaxf(val.w, 0.f));
        ((uint2*)out0)[idx] = oc;
    }
}

__global__ __launch_bounds__(256) void gather64_kernel(
    const __half* __restrict__ H, const float2* __restrict__ edges,
    const int* __restrict__ indptr,
    const float* __restrict__ bias, float* __restrict__ out)
{
    int node = (blockIdx.x * 256 + threadIdx.x) >> 4;
    int lane = threadIdx.x & 15;
    if (node >= N_NODES) return;

    int start = __ldg(&indptr[node]);
    int endp  = __ldg(&indptr[node + 1]);
    int cnt   = endp - start;
    int last  = endp - 1;

    float4 acc = make_float4(0.f, 0.f, 0.f, 0.f);
    const uint2* H2 = (const uint2*)H;

    if (cnt > 0) {
        float2 e0 = __ldg(&edges[start]);
        float2 e1 = __ldg(&edges[min(start + 1, last)]);
        int j = 0;
        for (; j + 1 < cnt; j += 2) {
            float2 n0 = __ldg(&edges[min(start + j + 2, last)]);
            float2 n1 = __ldg(&edges[min(start + j + 3, last)]);
            uint2 v0 = __ldg(&H2[(__float_as_int(e0.x) << 4) + lane]);
            uint2 v1 = __ldg(&H2[(__float_as_int(e1.x) << 4) + lane]);
            acc_h2(acc, v0, e0.y);
            acc_h2(acc, v1, e1.y);
            e0 = n0; e1 = n1;
        }
        if (j < cnt) {
            uint2 v0 = __ldg(&H2[(__float_as_int(e0.x) << 4) + lane]);
            acc_h2(acc, v0, e0.y);
        }
    }

    float4 bb = ((const float4*)bias)[lane];
    ((float4*)out)[(node << 4) + lane] =
        make_float4(acc.x + bb.x, acc.y + bb.y, acc.z + bb.z, acc.w + bb.w);
}

// ---------------------------------------------------------------------------

extern "C" void kernel_launch(void* const* d_in, const int* in_sizes, int n_in,
                              void* d_out, int out_size)
{
    const float* x  = (const float*)d_in[0];
    const int*   ei = (const int*)d_in[1];
    const float* ea = (const float*)d_in[2];
    const float* W1 = (const float*)d_in[3];
    const float* b1 = (const float*)d_in[4];
    const float* W2 = (const float*)d_in[5];
    const float* b2 = (const float*)d_in[6];
    const float* W3 = (const float*)d_in[7];
    const float* b3 = (const float*)d_in[8];
    float* out = (float*)d_out;

    const int N = N_NODES;
    const int E = N_EDGES;
    const int* src = ei;
    const int* dst = ei + E;

    __half *A, *B, *C;
    int *deg, *indptr, *cursor;
    float2* edges;
    cudaGetSymbolAddress((void**)&A, g_bufA);
    cudaGetSymbolAddress((void**)&B, g_bufB);
    cudaGetSymbolAddress((void**)&C, g_bufC);
    cudaGetSymbolAddress((void**)&deg, g_deg);
    cudaGetSymbolAddress((void**)&indptr, g_indptr);
    cudaGetSymbolAddress((void**)&cursor, g_cursor);
    cudaGetSymbolAddress((void**)&edges, g_edges);

    const int e_blocks    = (E + 255) / 256;
    const int g128_blocks = (N * 32 + 255) / 256;
    const int g64_blocks  = (N * 16 + 255) / 256;
    const int mrows       = (N + 63) / 64;

    dim3 grid128(mrows, 2);
    dim3 grid64(mrows, 1);

    cudaStream_t s2;
    cudaStreamCreateWithFlags(&s2, cudaStreamNonBlocking);
    cudaEvent_t evFork, evJoin;
    cudaEventCreateWithFlags(&evFork, cudaEventDisableTiming);
    cudaEventCreateWithFlags(&evJoin, cudaEventDisableTiming);

    // --- Fork: CSR build on s2 ∥ GEMM0 on main ---
    cudaEventRecord(evFork, 0);
    cudaStreamWaitEvent(s2, evFork, 0);

    cudaMemsetAsync(deg, 0, N * sizeof(int), s2);
    hist_kernel<<<e_blocks, 256, 0, s2>>>(dst, deg, E);
    scan_kernel<<<1, 1024, 0, s2>>>(deg, indptr, cursor);
    place_kernel<<<e_blocks, 256, 0, s2>>>(src, dst, ea, cursor, edges, E);
    cudaEventRecord(evJoin, s2);

    gemm_f16_kernel<128, 0><<<grid128, 128>>>(x, W1, A, N);

    cudaStreamWaitEvent(0, evJoin, 0);

    // --- Layer 0: B = x1 = agg(x@W1)+b1 ; C = x1 + relu(x1) ---
    gather128_kernel<0><<<g128_blocks, 256>>>(A, edges, indptr, b1, nullptr, B, C);

    // --- Layer 1: C = x1 + relu(agg(C@W2)+b2) ---
    gemm_f16_kernel<128, 1><<<grid128, 128>>>(C, W2, A, N);
    gather128_kernel<1><<<g128_blocks, 256>>>(A, edges, indptr, b2, B, C, nullptr);

    // --- Layer 2: out = agg(C@W3)+b3 ---
    gemm_f16_kernel<64, 1><<<grid64, 128>>>(C, W3, A, N);
    gather64_kernel<<<g64_blocks, 256>>>(A, edges, indptr, b3, out);
}

// round 15
// speedup vs baseline: 1.0747x; 1.0142x over previous
#include <cuda_runtime.h>
#include <cuda_fp16.h>
#include <cstdint>

// ---------------------------------------------------------------------------
// QGCN forward on GB300 — fp16 intermediate features.
//   GEMM: single-pass mma.sync.m16n8k16.f16 (R12 form).
//   XMODE 2 fuses x+relu(x) into the GEMM1 X-stager (gather0 writes 1 map).
//   Gathers: R12 2-edge pipeline (measured optimum).
//   CSR build forked under GEMM0.
// ---------------------------------------------------------------------------

#define N_NODES 50000
#define N_EDGES 800000

__device__ __half  g_bufA[N_NODES * 128];
__device__ __half  g_bufB[N_NODES * 128];
__device__ __half  g_bufC[N_NODES * 128];
__device__ int     g_deg[N_NODES];
__device__ int     g_indptr[N_NODES + 1];
__device__ int     g_cursor[N_NODES];
__device__ float2  g_edges[N_EDGES];   // {src (bit-cast int), weight}

// ---------------------------------------------------------------------------
__device__ __forceinline__ uint32_t pack_h2(float a, float b) {
    __half2 h = __floats2half2_rn(a, b);
    return *reinterpret_cast<uint32_t*>(&h);
}
__device__ __forceinline__ float2 unpack_h2(uint32_t w) {
    __half2 h = *reinterpret_cast<__half2*>(&w);
    return __half22float2(h);
}
// x + relu(x) on packed halves
__device__ __forceinline__ uint32_t resid_relu_h2(uint32_t w) {
    __half2 h = *reinterpret_cast<__half2*>(&w);
    __half2 z = __floats2half2_rn(0.f, 0.f);
    __half2 r = __hadd2(h, __hmax2(h, z));
    return *reinterpret_cast<uint32_t*>(&r);
}
__device__ __forceinline__ void mma_f16(
    float& d0, float& d1, float& d2, float& d3,
    uint32_t a0, uint32_t a1, uint32_t a2, uint32_t a3,
    uint32_t b0, uint32_t b1)
{
    asm volatile(
        "mma.sync.aligned.m16n8k16.row.col.f32.f16.f16.f32 "
        "{%0,%1,%2,%3},{%4,%5,%6,%7},{%8,%9},{%0,%1,%2,%3};"
        : "+f"(d0), "+f"(d1), "+f"(d2), "+f"(d3)
        : "r"(a0), "r"(a1), "r"(a2), "r"(a3), "r"(b0), "r"(b1));
}

// ---------------------------------------------------------------------------
// GEMM: Y[N, BNT](fp16) = f(X)[N, 128] @ W[128, BNT]
// XMODE: 0 = fp32 X, 1 = fp16 X, 2 = fp16 X with f(x)=x+relu(x) at staging.
// (R12 single-buffer structure — measured optimum.)
// ---------------------------------------------------------------------------
template <int BNT, int XMODE>
__global__ __launch_bounds__(128, 4) void gemm_f16_kernel(
    const void* __restrict__ Xv, const float* __restrict__ W,
    __half* __restrict__ Y, int N)
{
    constexpr int KC   = 32;
    constexpr int NK   = 128 / KC;
    constexpr int XSPW = 20;
    constexpr int WSPW = 72;

    __shared__ uint32_t Xs[64][XSPW];
    __shared__ uint32_t Ws[16][WSPW];

    const int tid  = threadIdx.x;
    const int lane = tid & 31;
    const int warp = tid >> 5;
    const int row0 = blockIdx.x * 64;
    const int nb   = blockIdx.y * 64;

    const int qr = lane >> 2;
    const int qt = lane & 3;
    const int wm = (warp & 1) * 32;
    const int wn = (warp >> 1) * 32;

    const float4* X4f = (const float4*)Xv;
    const uint4*  X4h = (const uint4*)Xv;
    const float4* W4  = (const float4*)W;

    float4 xrf[4];
    uint4  xrh[2];
    float4 wrA[2], wrB[2];

    auto ldgX = [&](int ch) {
        if (XMODE != 0) {
#pragma unroll
            for (int i = 0; i < 2; i++) {
                int idx = tid + i * 128;
                int r = idx >> 2, c4 = idx & 3;
                int gr = row0 + r;
                xrh[i] = (gr < N) ? X4h[gr * 16 + ch * 4 + c4]
                                  : make_uint4(0, 0, 0, 0);
            }
        } else {
#pragma unroll
            for (int i = 0; i < 4; i++) {
                int idx = tid + i * 128;
                int r = idx >> 3, c4 = idx & 7;
                int gr = row0 + r;
                xrf[i] = (gr < N) ? X4f[gr * 32 + ch * 8 + c4]
                                  : make_float4(0.f, 0.f, 0.f, 0.f);
            }
        }
    };
    auto ldgW = [&](int ch) {
#pragma unroll
        for (int i = 0; i < 2; i++) {
            int idx = tid + i * 128;
            int kp = idx >> 4, cc = idx & 15;
            wrA[i] = W4[(((ch * KC + 2 * kp)     * BNT + nb) >> 2) + cc];
            wrB[i] = W4[(((ch * KC + 2 * kp + 1) * BNT + nb) >> 2) + cc];
        }
    };
    auto xform = [](uint32_t w) {
        return (XMODE == 2) ? resid_relu_h2(w) : w;
    };
    auto stsX = [&]() {
        if (XMODE != 0) {
#pragma unroll
            for (int i = 0; i < 2; i++) {
                int idx = tid + i * 128;
                int r = idx >> 2, c4 = idx & 3;
                Xs[r][c4 * 4 + 0] = xform(xrh[i].x);
                Xs[r][c4 * 4 + 1] = xform(xrh[i].y);
                Xs[r][c4 * 4 + 2] = xform(xrh[i].z);
                Xs[r][c4 * 4 + 3] = xform(xrh[i].w);
            }
        } else {
#pragma unroll
            for (int i = 0; i < 4; i++) {
                int idx = tid + i * 128;
                int r = idx >> 3, c4 = idx & 7;
                Xs[r][c4 * 2 + 0] = pack_h2(xrf[i].x, xrf[i].y);
                Xs[r][c4 * 2 + 1] = pack_h2(xrf[i].z, xrf[i].w);
            }
        }
    };
    auto stsW = [&]() {
#pragma unroll
        for (int i = 0; i < 2; i++) {
            int idx = tid + i * 128;
            int kp = idx >> 4, cc = idx & 15;
            const float* a = (const float*)&wrA[i];
            const float* b = (const float*)&wrB[i];
#pragma unroll
            for (int j = 0; j < 4; j++)
                Ws[kp][cc * 4 + j] = pack_h2(a[j], b[j]);
        }
    };

    float acc[2][4][4] = {};

    ldgX(0); ldgW(0);
    stsX(); stsW();
    __syncthreads();

#pragma unroll
    for (int ch = 0; ch < NK; ch++) {
        if (ch + 1 < NK) { ldgX(ch + 1); ldgW(ch + 1); }

#pragma unroll
        for (int ks = 0; ks < 2; ks++) {
            const int kw = ks * 8 + qt;

            uint32_t a[2][4];
#pragma unroll
            for (int mt = 0; mt < 2; mt++) {
                int r = wm + mt * 16 + qr;
                a[mt][0] = Xs[r][kw];
                a[mt][1] = Xs[r + 8][kw];
                a[mt][2] = Xs[r][kw + 4];
                a[mt][3] = Xs[r + 8][kw + 4];
            }
            uint32_t b[4][2];
#pragma unroll
            for (int nt = 0; nt < 4; nt++) {
                int c = wn + nt * 8 + qr;
                b[nt][0] = Ws[ks * 8 + qt][c];
                b[nt][1] = Ws[ks * 8 + qt + 4][c];
            }
#pragma unroll
            for (int mt = 0; mt < 2; mt++)
#pragma unroll
                for (int nt = 0; nt < 4; nt++) {
                    float* d = acc[mt][nt];
                    mma_f16(d[0], d[1], d[2], d[3],
                            a[mt][0], a[mt][1], a[mt][2], a[mt][3],
                            b[nt][0], b[nt][1]);
                }
        }

        if (ch + 1 < NK) {
            __syncthreads();
            stsX(); stsW();
            __syncthreads();
        }
    }

    uint32_t* Y32 = (uint32_t*)Y;
#pragma unroll
    for (int mt = 0; mt < 2; mt++) {
#pragma unroll
        for (int nt = 0; nt < 4; nt++) {
            int gc = nb + wn + nt * 8 + qt * 2;
            int r0g = row0 + wm + mt * 16 + qr;
            if (r0g < N)
                Y32[(r0g * BNT + gc) >> 1] = pack_h2(acc[mt][nt][0], acc[mt][nt][1]);
            int r1g = r0g + 8;
            if (r1g < N)
                Y32[(r1g * BNT + gc) >> 1] = pack_h2(acc[mt][nt][2], acc[mt][nt][3]);
        }
    }
}

// ---------------------------------------------------------------------------
// CSR build
// ---------------------------------------------------------------------------
__global__ __launch_bounds__(256) void hist_kernel(
    const int* __restrict__ dst, int* __restrict__ deg, int E)
{
    int e = blockIdx.x * blockDim.x + threadIdx.x;
    if (e < E) atomicAdd(&deg[__ldg(&dst[e])], 1);
}

__global__ __launch_bounds__(1024) void scan_kernel(
    const int* __restrict__ deg, int* __restrict__ indptr,
    int* __restrict__ cursor)
{
    __shared__ int sh[1024];
    const int CHUNK = (N_NODES + 1023) / 1024;
    int t = threadIdx.x;
    int begin = t * CHUNK;
    int end   = begin + CHUNK; if (end > N_NODES) end = N_NODES;

    int s = 0;
    for (int i = begin; i < end; i++) s += deg[i];
    sh[t] = s;
    __syncthreads();

    for (int off = 1; off < 1024; off <<= 1) {
        int v = sh[t];
        int a = (t >= off) ? sh[t - off] : 0;
        __syncthreads();
        sh[t] = v + a;
        __syncthreads();
    }

    int run = (t == 0) ? 0 : sh[t - 1];
    for (int i = begin; i < end; i++) {
        indptr[i] = run;
        cursor[i] = run;
        run += deg[i];
    }
    if (t == 1023) indptr[N_NODES] = run;
}

__global__ __launch_bounds__(256) void place_kernel(
    const int* __restrict__ src, const int* __restrict__ dst,
    const float* __restrict__ ew, int* __restrict__ cursor,
    float2* __restrict__ edges, int E)
{
    int e = blockIdx.x * blockDim.x + threadIdx.x;
    if (e >= E) return;
    int d = __ldg(&dst[e]);
    int p = atomicAdd(&cursor[d], 1);
    edges[p] = make_float2(__int_as_float(__ldg(&src[e])), __ldg(&ew[e]));
}

// ---------------------------------------------------------------------------
// Gather helpers (R12 2-edge pipeline — measured optimum)
// ---------------------------------------------------------------------------
__device__ __forceinline__ void acc_h2(float4& acc, uint2 u, float w) {
    float2 f0 = unpack_h2(u.x);
    float2 f1 = unpack_h2(u.y);
    acc.x = fmaf(f0.x, w, acc.x); acc.y = fmaf(f0.y, w, acc.y);
    acc.z = fmaf(f1.x, w, acc.z); acc.w = fmaf(f1.y, w, acc.w);
}

// MODE 0: out0 = val                      (layer 0; residual fused into GEMM1)
// MODE 1: out0 = Bres + relu(val)         (layer 1)
template <int MODE>
__global__ __launch_bounds__(256) void gather128_kernel(
    const __half* __restrict__ H, const float2* __restrict__ edges,
    const int* __restrict__ indptr,
    const float* __restrict__ bias, const __half* __restrict__ Bres,
    __half* __restrict__ out0)
{
    int node = (blockIdx.x * 256 + threadIdx.x) >> 5;
    int lane = threadIdx.x & 31;
    if (node >= N_NODES) return;

    int start = __ldg(&indptr[node]);
    int endp  = __ldg(&indptr[node + 1]);
    int cnt   = endp - start;
    int last  = endp - 1;

    float4 acc = make_float4(0.f, 0.f, 0.f, 0.f);
    const uint2* H2 = (const uint2*)H;

    if (cnt > 0) {
        float2 e0 = __ldg(&edges[start]);
        float2 e1 = __ldg(&edges[min(start + 1, last)]);
        int j = 0;
        for (; j + 1 < cnt; j += 2) {
            float2 n0 = __ldg(&edges[min(start + j + 2, last)]);
            float2 n1 = __ldg(&edges[min(start + j + 3, last)]);
            uint2 v0 = __ldg(&H2[(__float_as_int(e0.x) << 5) + lane]);
            uint2 v1 = __ldg(&H2[(__float_as_int(e1.x) << 5) + lane]);
            acc_h2(acc, v0, e0.y);
            acc_h2(acc, v1, e1.y);
            e0 = n0; e1 = n1;
        }
        if (j < cnt) {
            uint2 v0 = __ldg(&H2[(__float_as_int(e0.x) << 5) + lane]);
            acc_h2(acc, v0, e0.y);
        }
    }

    float4 bb = ((const float4*)bias)[lane];
    float4 val = make_float4(acc.x + bb.x, acc.y + bb.y,
                             acc.z + bb.z, acc.w + bb.w);
    int idx = (node << 5) + lane;

    if (MODE == 0) {
        uint2 ov;
        ov.x = pack_h2(val.x, val.y);
        ov.y = pack_h2(val.z, val.w);
        ((uint2*)out0)[idx] = ov;
    } else {
        uint2 bu = __ldg(&((const uint2*)Bres)[idx]);
        float2 b0 = unpack_h2(bu.x);
        float2 b1 = unpack_h2(bu.y);
        uint2 oc;
        oc.x = pack_h2(b0.x + fmaxf(val.x, 0.f), b0.y + fmaxf(val.y, 0.f));
        oc.y = pack_h2(b1.x + fmaxf(val.z, 0.f), b1.y + fmaxf(val.w, 0.f));
        ((uint2*)out0)[idx] = oc;
    }
}

__global__ __launch_bounds__(256) void gather64_kernel(
    const __half* __restrict__ H, const float2* __restrict__ edges,
    const int* __restrict__ indptr,
    const float* __restrict__ bias, float* __restrict__ out)
{
    int node = (blockIdx.x * 256 + threadIdx.x) >> 4;
    int lane = threadIdx.x & 15;
    if (node >= N_NODES) return;

    int start = __ldg(&indptr[node]);
    int endp  = __ldg(&indptr[node + 1]);
    int cnt   = endp - start;
    int last  = endp - 1;

    float4 acc = make_float4(0.f, 0.f, 0.f, 0.f);
    const uint2* H2 = (const uint2*)H;

    if (cnt > 0) {
        float2 e0 = __ldg(&edges[start]);
        float2 e1 = __ldg(&edges[min(start + 1, last)]);
        int j = 0;
        for (; j + 1 < cnt; j += 2) {
            float2 n0 = __ldg(&edges[min(start + j + 2, last)]);
            float2 n1 = __ldg(&edges[min(start + j + 3, last)]);
            uint2 v0 = __ldg(&H2[(__float_as_int(e0.x) << 4) + lane]);
            uint2 v1 = __ldg(&H2[(__float_as_int(e1.x) << 4) + lane]);
            acc_h2(acc, v0, e0.y);
            acc_h2(acc, v1, e1.y);
            e0 = n0; e1 = n1;
        }
        if (j < cnt) {
            uint2 v0 = __ldg(&H2[(__float_as_int(e0.x) << 4) + lane]);
            acc_h2(acc, v0, e0.y);
        }
    }

    float4 bb = ((const float4*)bias)[lane];
    ((float4*)out)[(node << 4) + lane] =
        make_float4(acc.x + bb.x, acc.y + bb.y, acc.z + bb.z, acc.w + bb.w);
}

// ---------------------------------------------------------------------------

extern "C" void kernel_launch(void* const* d_in, const int* in_sizes, int n_in,
                              void* d_out, int out_size)
{
    const float* x  = (const float*)d_in[0];
    const int*   ei = (const int*)d_in[1];
    const float* ea = (const float*)d_in[2];
    const float* W1 = (const float*)d_in[3];
    const float* b1 = (const float*)d_in[4];
    const float* W2 = (const float*)d_in[5];
    const float* b2 = (const float*)d_in[6];
    const float* W3 = (const float*)d_in[7];
    const float* b3 = (const float*)d_in[8];
    float* out = (float*)d_out;

    const int N = N_NODES;
    const int E = N_EDGES;
    const int* src = ei;
    const int* dst = ei + E;

    __half *A, *B, *C;
    int *deg, *indptr, *cursor;
    float2* edges;
    cudaGetSymbolAddress((void**)&A, g_bufA);
    cudaGetSymbolAddress((void**)&B, g_bufB);
    cudaGetSymbolAddress((void**)&C, g_bufC);
    cudaGetSymbolAddress((void**)&deg, g_deg);
    cudaGetSymbolAddress((void**)&indptr, g_indptr);
    cudaGetSymbolAddress((void**)&cursor, g_cursor);
    cudaGetSymbolAddress((void**)&edges, g_edges);

    const int e_blocks    = (E + 255) / 256;
    const int g128_blocks = (N * 32 + 255) / 256;
    const int g64_blocks  = (N * 16 + 255) / 256;
    const int mrows       = (N + 63) / 64;

    dim3 grid128(mrows, 2);
    dim3 grid64(mrows, 1);

    cudaStream_t s2;
    cudaStreamCreateWithFlags(&s2, cudaStreamNonBlocking);
    cudaEvent_t evFork, evJoin;
    cudaEventCreateWithFlags(&evFork, cudaEventDisableTiming);
    cudaEventCreateWithFlags(&evJoin, cudaEventDisableTiming);

    // --- Fork: CSR build on s2 ∥ GEMM0 on main ---
    cudaEventRecord(evFork, 0);
    cudaStreamWaitEvent(s2, evFork, 0);

    cudaMemsetAsync(deg, 0, N * sizeof(int), s2);
    hist_kernel<<<e_blocks, 256, 0, s2>>>(dst, deg, E);
    scan_kernel<<<1, 1024, 0, s2>>>(deg, indptr, cursor);
    place_kernel<<<e_blocks, 256, 0, s2>>>(src, dst, ea, cursor, edges, E);
    cudaEventRecord(evJoin, s2);

    gemm_f16_kernel<128, 0><<<grid128, 128>>>(x, W1, A, N);

    cudaStreamWaitEvent(0, evJoin, 0);

    // --- Layer 0: B = x1 = agg(x@W1)+b1  (residual fused into GEMM1) ---
    gather128_kernel<0><<<g128_blocks, 256>>>(A, edges, indptr, b1, nullptr, B);

    // --- Layer 1: A = (B + relu(B)) @ W2 ; C = B + relu(agg+b2) ---
    gemm_f16_kernel<128, 2><<<grid128, 128>>>(B, W2, A, N);
    gather128_kernel<1><<<g128_blocks, 256>>>(A, edges, indptr, b2, B, C);

    // --- Layer 2: out = agg(C@W3)+b3 ---
    gemm_f16_kernel<64, 1><<<grid64, 128>>>(C, W3, A, N);
    gather64_kernel<<<g64_blocks, 256>>>(A, edges, indptr, b3, out);
}

// round 17
// speedup vs baseline: 1.0967x; 1.0204x over previous
#include <cuda_runtime.h>
#include <cuda_fp16.h>
#include <cstdint>

// ---------------------------------------------------------------------------
// QGCN forward on GB300 — fp16 intermediate features.
//   GEMM (D=128 out): 128x128 block tile, 256 thr, warp tile 32x64.
//                     (WSPW fixed to 136 — R16 had an OOB smem index.)
//   GEMM (D=64 out):  R12 64x64 kernel (measured good).
//   Gathers: R12 2-edge pipeline (measured optimum).
//   CSR build forked under GEMM0.
// ---------------------------------------------------------------------------

#define N_NODES 50000
#define N_EDGES 800000

__device__ __half  g_bufA[N_NODES * 128];
__device__ __half  g_bufB[N_NODES * 128];
__device__ __half  g_bufC[N_NODES * 128];
__device__ int     g_deg[N_NODES];
__device__ int     g_indptr[N_NODES + 1];
__device__ int     g_cursor[N_NODES];
__device__ float2  g_edges[N_EDGES];   // {src (bit-cast int), weight}

// ---------------------------------------------------------------------------
__device__ __forceinline__ uint32_t pack_h2(float a, float b) {
    __half2 h = __floats2half2_rn(a, b);
    return *reinterpret_cast<uint32_t*>(&h);
}
__device__ __forceinline__ float2 unpack_h2(uint32_t w) {
    __half2 h = *reinterpret_cast<__half2*>(&w);
    return __half22float2(h);
}
__device__ __forceinline__ void mma_f16(
    float& d0, float& d1, float& d2, float& d3,
    uint32_t a0, uint32_t a1, uint32_t a2, uint32_t a3,
    uint32_t b0, uint32_t b1)
{
    asm volatile(
        "mma.sync.aligned.m16n8k16.row.col.f32.f16.f16.f32 "
        "{%0,%1,%2,%3},{%4,%5,%6,%7},{%8,%9},{%0,%1,%2,%3};"
        : "+f"(d0), "+f"(d1), "+f"(d2), "+f"(d3)
        : "r"(a0), "r"(a1), "r"(a2), "r"(a3), "r"(b0), "r"(b1));
}

// ---------------------------------------------------------------------------
// Big GEMM: Y[N, 128](fp16) = X[N, 128] @ W[128, 128]
// 128x128 block, 256 threads (8 warps: 4 along M, 2 along N; warp 32x64).
// XMODE: 0 = fp32 X, 1 = fp16 X.
// ---------------------------------------------------------------------------
template <int XMODE>
__global__ __launch_bounds__(256, 2) void gemm_big_kernel(
    const void* __restrict__ Xv, const float* __restrict__ W,
    __half* __restrict__ Y, int N)
{
    constexpr int KC   = 32;
    constexpr int NK   = 128 / KC;
    constexpr int XSPW = 20;      // words per X row (16 + pad)
    constexpr int WSPW = 136;     // words per W k-pair row (128 + 8 pad)

    __shared__ uint32_t Xs[128][XSPW];
    __shared__ uint32_t Ws[16][WSPW];

    const int tid  = threadIdx.x;
    const int lane = tid & 31;
    const int warp = tid >> 5;
    const int row0 = blockIdx.x * 128;

    const int qr = lane >> 2;
    const int qt = lane & 3;
    const int wm = (warp & 3) * 32;        // 4 warps along M
    const int wn = (warp >> 2) * 64;       // 2 warps along N

    const float4* X4f = (const float4*)Xv;
    const uint4*  X4h = (const uint4*)Xv;
    const float4* W4  = (const float4*)W;

    float4 xrf[4];
    uint4  xrh[2];
    float4 wrA[2], wrB[2];

    auto ldgX = [&](int ch) {
        if (XMODE != 0) {
#pragma unroll
            for (int i = 0; i < 2; i++) {
                int idx = tid + i * 256;          // 128 rows * 4 uint4
                int r = idx >> 2, c4 = idx & 3;
                int gr = row0 + r;
                xrh[i] = (gr < N) ? X4h[gr * 16 + ch * 4 + c4]
                                  : make_uint4(0, 0, 0, 0);
            }
        } else {
#pragma unroll
            for (int i = 0; i < 4; i++) {
                int idx = tid + i * 256;          // 128 rows * 8 float4
                int r = idx >> 3, c4 = idx & 7;
                int gr = row0 + r;
                xrf[i] = (gr < N) ? X4f[gr * 32 + ch * 8 + c4]
                                  : make_float4(0.f, 0.f, 0.f, 0.f);
            }
        }
    };
    auto ldgW = [&](int ch) {
#pragma unroll
        for (int i = 0; i < 2; i++) {
            int idx = tid + i * 256;              // 16 kpairs * 32 col4
            int kp = idx >> 5, cc = idx & 31;
            wrA[i] = W4[(ch * KC + 2 * kp)     * 32 + cc];
            wrB[i] = W4[(ch * KC + 2 * kp + 1) * 32 + cc];
        }
    };
    auto stsX = [&]() {
        if (XMODE != 0) {
#pragma unroll
            for (int i = 0; i < 2; i++) {
                int idx = tid + i * 256;
                int r = idx >> 2, c4 = idx & 3;
                Xs[r][c4 * 4 + 0] = xrh[i].x;
                Xs[r][c4 * 4 + 1] = xrh[i].y;
                Xs[r][c4 * 4 + 2] = xrh[i].z;
                Xs[r][c4 * 4 + 3] = xrh[i].w;
            }
        } else {
#pragma unroll
            for (int i = 0; i < 4; i++) {
                int idx = tid + i * 256;
                int r = idx >> 3, c4 = idx & 7;
                Xs[r][c4 * 2 + 0] = pack_h2(xrf[i].x, xrf[i].y);
                Xs[r][c4 * 2 + 1] = pack_h2(xrf[i].z, xrf[i].w);
            }
        }
    };
    auto stsW = [&]() {
#pragma unroll
        for (int i = 0; i < 2; i++) {
            int idx = tid + i * 256;
            int kp = idx >> 5, cc = idx & 31;
            const float* a = (const float*)&wrA[i];
            const float* b = (const float*)&wrB[i];
#pragma unroll
            for (int j = 0; j < 4; j++)
                Ws[kp][cc * 4 + j] = pack_h2(a[j], b[j]);   // (k even, k odd)
        }
    };

    float acc[2][8][4] = {};

    ldgX(0); ldgW(0);
    stsX(); stsW();
    __syncthreads();

#pragma unroll
    for (int ch = 0; ch < NK; ch++) {
        if (ch + 1 < NK) { ldgX(ch + 1); ldgW(ch + 1); }

#pragma unroll
        for (int ks = 0; ks < 2; ks++) {
            const int kw = ks * 8 + qt;

            uint32_t a[2][4];
#pragma unroll
            for (int mt = 0; mt < 2; mt++) {
                int r = wm + mt * 16 + qr;
                a[mt][0] = Xs[r][kw];
                a[mt][1] = Xs[r + 8][kw];
                a[mt][2] = Xs[r][kw + 4];
                a[mt][3] = Xs[r + 8][kw + 4];
            }
            uint32_t b[8][2];
#pragma unroll
            for (int nt = 0; nt < 8; nt++) {
                int c = wn + nt * 8 + qr;
                b[nt][0] = Ws[ks * 8 + qt][c];
                b[nt][1] = Ws[ks * 8 + qt + 4][c];
            }
#pragma unroll
            for (int mt = 0; mt < 2; mt++)
#pragma unroll
                for (int nt = 0; nt < 8; nt++) {
                    float* d = acc[mt][nt];
                    mma_f16(d[0], d[1], d[2], d[3],
                            a[mt][0], a[mt][1], a[mt][2], a[mt][3],
                            b[nt][0], b[nt][1]);
                }
        }

        if (ch + 1 < NK) {
            __syncthreads();
            stsX(); stsW();
            __syncthreads();
        }
    }

    uint32_t* Y32 = (uint32_t*)Y;
#pragma unroll
    for (int mt = 0; mt < 2; mt++) {
#pragma unroll
        for (int nt = 0; nt < 8; nt++) {
            int gc = wn + nt * 8 + qt * 2;
            int r0g = row0 + wm + mt * 16 + qr;
            if (r0g < N)
                Y32[(r0g * 128 + gc) >> 1] = pack_h2(acc[mt][nt][0], acc[mt][nt][1]);
            int r1g = r0g + 8;
            if (r1g < N)
                Y32[(r1g * 128 + gc) >> 1] = pack_h2(acc[mt][nt][2], acc[mt][nt][3]);
        }
    }
}

// ---------------------------------------------------------------------------
// R12 GEMM (used for BNT=64 last layer): 64x64 block, 128 threads.
// ---------------------------------------------------------------------------
template <int BNT, int XHALF>
__global__ __launch_bounds__(128, 4) void gemm_f16_kernel(
    const void* __restrict__ Xv, const float* __restrict__ W,
    __half* __restrict__ Y, int N)
{
    constexpr int KC   = 32;
    constexpr int NK   = 128 / KC;
    constexpr int XSPW = 20;
    constexpr int WSPW = 72;

    __shared__ uint32_t Xs[64][XSPW];
    __shared__ uint32_t Ws[16][WSPW];

    const int tid  = threadIdx.x;
    const int lane = tid & 31;
    const int warp = tid >> 5;
    const int row0 = blockIdx.x * 64;
    const int nb   = blockIdx.y * 64;

    const int qr = lane >> 2;
    const int qt = lane & 3;
    const int wm = (warp & 1) * 32;
    const int wn = (warp >> 1) * 32;

    const float4* X4f = (const float4*)Xv;
    const uint4*  X4h = (const uint4*)Xv;
    const float4* W4  = (const float4*)W;

    float4 xrf[4];
    uint4  xrh[2];
    float4 wrA[2], wrB[2];

    auto ldgX = [&](int ch) {
        if (XHALF) {
#pragma unroll
            for (int i = 0; i < 2; i++) {
                int idx = tid + i * 128;
                int r = idx >> 2, c4 = idx & 3;
                int gr = row0 + r;
                xrh[i] = (gr < N) ? X4h[gr * 16 + ch * 4 + c4]
                                  : make_uint4(0, 0, 0, 0);
            }
        } else {
#pragma unroll
            for (int i = 0; i < 4; i++) {
                int idx = tid + i * 128;
                int r = idx >> 3, c4 = idx & 7;
                int gr = row0 + r;
                xrf[i] = (gr < N) ? X4f[gr * 32 + ch * 8 + c4]
                                  : make_float4(0.f, 0.f, 0.f, 0.f);
            }
        }
    };
    auto ldgW = [&](int ch) {
#pragma unroll
        for (int i = 0; i < 2; i++) {
            int idx = tid + i * 128;
            int kp = idx >> 4, cc = idx & 15;
            wrA[i] = W4[(((ch * KC + 2 * kp)     * BNT + nb) >> 2) + cc];
            wrB[i] = W4[(((ch * KC + 2 * kp + 1) * BNT + nb) >> 2) + cc];
        }
    };
    auto stsX = [&]() {
        if (XHALF) {
#pragma unroll
            for (int i = 0; i < 2; i++) {
                int idx = tid + i * 128;
                int r = idx >> 2, c4 = idx & 3;
                Xs[r][c4 * 4 + 0] = xrh[i].x;
                Xs[r][c4 * 4 + 1] = xrh[i].y;
                Xs[r][c4 * 4 + 2] = xrh[i].z;
                Xs[r][c4 * 4 + 3] = xrh[i].w;
            }
        } else {
#pragma unroll
            for (int i = 0; i < 4; i++) {
                int idx = tid + i * 128;
                int r = idx >> 3, c4 = idx & 7;
                Xs[r][c4 * 2 + 0] = pack_h2(xrf[i].x, xrf[i].y);
                Xs[r][c4 * 2 + 1] = pack_h2(xrf[i].z, xrf[i].w);
            }
        }
    };
    auto stsW = [&]() {
#pragma unroll
        for (int i = 0; i < 2; i++) {
            int idx = tid + i * 128;
            int kp = idx >> 4, cc = idx & 15;
            const float* a = (const float*)&wrA[i];
            const float* b = (const float*)&wrB[i];
#pragma unroll
            for (int j = 0; j < 4; j++)
                Ws[kp][cc * 4 + j] = pack_h2(a[j], b[j]);
        }
    };

    float acc[2][4][4] = {};

    ldgX(0); ldgW(0);
    stsX(); stsW();
    __syncthreads();

#pragma unroll
    for (int ch = 0; ch < NK; ch++) {
        if (ch + 1 < NK) { ldgX(ch + 1); ldgW(ch + 1); }

#pragma unroll
        for (int ks = 0; ks < 2; ks++) {
            const int kw = ks * 8 + qt;

            uint32_t a[2][4];
#pragma unroll
            for (int mt = 0; mt < 2; mt++) {
                int r = wm + mt * 16 + qr;
                a[mt][0] = Xs[r][kw];
                a[mt][1] = Xs[r + 8][kw];
                a[mt][2] = Xs[r][kw + 4];
                a[mt][3] = Xs[r + 8][kw + 4];
            }
            uint32_t b[4][2];
#pragma unroll
            for (int nt = 0; nt < 4; nt++) {
                int c = wn + nt * 8 + qr;
                b[nt][0] = Ws[ks * 8 + qt][c];
                b[nt][1] = Ws[ks * 8 + qt + 4][c];
            }
#pragma unroll
            for (int mt = 0; mt < 2; mt++)
#pragma unroll
                for (int nt = 0; nt < 4; nt++) {
                    float* d = acc[mt][nt];
                    mma_f16(d[0], d[1], d[2], d[3],
                            a[mt][0], a[mt][1], a[mt][2], a[mt][3],
                            b[nt][0], b[nt][1]);
                }
        }

        if (ch + 1 < NK) {
            __syncthreads();
            stsX(); stsW();
            __syncthreads();
        }
    }

    uint32_t* Y32 = (uint32_t*)Y;
#pragma unroll
    for (int mt = 0; mt < 2; mt++) {
#pragma unroll
        for (int nt = 0; nt < 4; nt++) {
            int gc = nb + wn + nt * 8 + qt * 2;
            int r0g = row0 + wm + mt * 16 + qr;
            if (r0g < N)
                Y32[(r0g * BNT + gc) >> 1] = pack_h2(acc[mt][nt][0], acc[mt][nt][1]);
            int r1g = r0g + 8;
            if (r1g < N)
                Y32[(r1g * BNT + gc) >> 1] = pack_h2(acc[mt][nt][2], acc[mt][nt][3]);
        }
    }
}

// ---------------------------------------------------------------------------
// CSR build
// ---------------------------------------------------------------------------
__global__ __launch_bounds__(256) void hist_kernel(
    const int* __restrict__ dst, int* __restrict__ deg, int E)
{
    int e = blockIdx.x * blockDim.x + threadIdx.x;
    if (e < E) atomicAdd(&deg[__ldg(&dst[e])], 1);
}

__global__ __launch_bounds__(1024) void scan_kernel(
    const int* __restrict__ deg, int* __restrict__ indptr,
    int* __restrict__ cursor)
{
    __shared__ int sh[1024];
    const int CHUNK = (N_NODES + 1023) / 1024;
    int t = threadIdx.x;
    int begin = t * CHUNK;
    int end   = begin + CHUNK; if (end > N_NODES) end = N_NODES;

    int s = 0;
    for (int i = begin; i < end; i++) s += deg[i];
    sh[t] = s;
    __syncthreads();

    for (int off = 1; off < 1024; off <<= 1) {
        int v = sh[t];
        int a = (t >= off) ? sh[t - off] : 0;
        __syncthreads();
        sh[t] = v + a;
        __syncthreads();
    }

    int run = (t == 0) ? 0 : sh[t - 1];
    for (int i = begin; i < end; i++) {
        indptr[i] = run;
        cursor[i] = run;
        run += deg[i];
    }
    if (t == 1023) indptr[N_NODES] = run;
}

__global__ __launch_bounds__(256) void place_kernel(
    const int* __restrict__ src, const int* __restrict__ dst,
    const float* __restrict__ ew, int* __restrict__ cursor,
    float2* __restrict__ edges, int E)
{
    int e = blockIdx.x * blockDim.x + threadIdx.x;
    if (e >= E) return;
    int d = __ldg(&dst[e]);
    int p = atomicAdd(&cursor[d], 1);
    edges[p] = make_float2(__int_as_float(__ldg(&src[e])), __ldg(&ew[e]));
}

// ---------------------------------------------------------------------------
// Gather helpers (R12 2-edge pipeline — measured optimum)
// ---------------------------------------------------------------------------
__device__ __forceinline__ void acc_h2(float4& acc, uint2 u, float w) {
    float2 f0 = unpack_h2(u.x);
    float2 f1 = unpack_h2(u.y);
    acc.x = fmaf(f0.x, w, acc.x); acc.y = fmaf(f0.y, w, acc.y);
    acc.z = fmaf(f1.x, w, acc.z); acc.w = fmaf(f1.y, w, acc.w);
}

// MODE 0: out0 = val; out1 = val + relu(val)   (layer 0)
// MODE 1: out0 = Bres + relu(val)              (layer 1)
template <int MODE>
__global__ __launch_bounds__(256) void gather128_kernel(
    const __half* __restrict__ H, const float2* __restrict__ edges,
    const int* __restrict__ indptr,
    const float* __restrict__ bias, const __half* __restrict__ Bres,
    __half* __restrict__ out0, __half* __restrict__ out1)
{
    int node = (blockIdx.x * 256 + threadIdx.x) >> 5;
    int lane = threadIdx.x & 31;
    if (node >= N_NODES) return;

    int start = __ldg(&indptr[node]);
    int endp  = __ldg(&indptr[node + 1]);
    int cnt   = endp - start;
    int last  = endp - 1;

    float4 acc = make_float4(0.f, 0.f, 0.f, 0.f);
    const uint2* H2 = (const uint2*)H;

    if (cnt > 0) {
        float2 e0 = __ldg(&edges[start]);
        float2 e1 = __ldg(&edges[min(start + 1, last)]);
        int j = 0;
        for (; j + 1 < cnt; j += 2) {
            float2 n0 = __ldg(&edges[min(start + j + 2, last)]);
            float2 n1 = __ldg(&edges[min(start + j + 3, last)]);
            uint2 v0 = __ldg(&H2[(__float_as_int(e0.x) << 5) + lane]);
            uint2 v1 = __ldg(&H2[(__float_as_int(e1.x) << 5) + lane]);
            acc_h2(acc, v0, e0.y);
            acc_h2(acc, v1, e1.y);
            e0 = n0; e1 = n1;
        }
        if (j < cnt) {
            uint2 v0 = __ldg(&H2[(__float_as_int(e0.x) << 5) + lane]);
            acc_h2(acc, v0, e0.y);
        }
    }

    float4 bb = ((const float4*)bias)[lane];
    float4 val = make_float4(acc.x + bb.x, acc.y + bb.y,
                             acc.z + bb.z, acc.w + bb.w);
    int idx = (node << 5) + lane;

    if (MODE == 0) {
        uint2 ov;
        ov.x = pack_h2(val.x, val.y);
        ov.y = pack_h2(val.z, val.w);
        ((uint2*)out0)[idx] = ov;
        uint2 oc;
        oc.x = pack_h2(val.x + fmaxf(val.x, 0.f), val.y + fmaxf(val.y, 0.f));
        oc.y = pack_h2(val.z + fmaxf(val.z, 0.f), val.w + fmaxf(val.w, 0.f));
        ((uint2*)out1)[idx] = oc;
    } else {
        uint2 bu = __ldg(&((const uint2*)Bres)[idx]);
        float2 b0 = unpack_h2(bu.x);
        float2 b1 = unpack_h2(bu.y);
        uint2 oc;
        oc.x = pack_h2(b0.x + fmaxf(val.x, 0.f), b0.y + fmaxf(val.y, 0.f));
        oc.y = pack_h2(b1.x + fmaxf(val.z, 0.f), b1.y + fmaxf(val.w, 0.f));
        ((uint2*)out0)[idx] = oc;
    }
}

__global__ __launch_bounds__(256) void gather64_kernel(
    const __half* __restrict__ H, const float2* __restrict__ edges,
    const int* __restrict__ indptr,
    const float* __restrict__ bias, float* __restrict__ out)
{
    int node = (blockIdx.x * 256 + threadIdx.x) >> 4;
    int lane = threadIdx.x & 15;
    if (node >= N_NODES) return;

    int start = __ldg(&indptr[node]);
    int endp  = __ldg(&indptr[node + 1]);
    int cnt   = endp - start;
    int last  = endp - 1;

    float4 acc = make_float4(0.f, 0.f, 0.f, 0.f);
    const uint2* H2 = (const uint2*)H;

    if (cnt > 0) {
        float2 e0 = __ldg(&edges[start]);
        float2 e1 = __ldg(&edges[min(start + 1, last)]);
        int j = 0;
        for (; j + 1 < cnt; j += 2) {
            float2 n0 = __ldg(&edges[min(start + j + 2, last)]);
            float2 n1 = __ldg(&edges[min(start + j + 3, last)]);
            uint2 v0 = __ldg(&H2[(__float_as_int(e0.x) << 4) + lane]);
            uint2 v1 = __ldg(&H2[(__float_as_int(e1.x) << 4) + lane]);
            acc_h2(acc, v0, e0.y);
            acc_h2(acc, v1, e1.y);
            e0 = n0; e1 = n1;
        }
        if (j < cnt) {
            uint2 v0 = __ldg(&H2[(__float_as_int(e0.x) << 4) + lane]);
            acc_h2(acc, v0, e0.y);
        }
    }

    float4 bb = ((const float4*)bias)[lane];
    ((float4*)out)[(node << 4) + lane] =
        make_float4(acc.x + bb.x, acc.y + bb.y, acc.z + bb.z, acc.w + bb.w);
}

// ---------------------------------------------------------------------------

extern "C" void kernel_launch(void* const* d_in, const int* in_sizes, int n_in,
                              void* d_out, int out_size)
{
    const float* x  = (const float*)d_in[0];
    const int*   ei = (const int*)d_in[1];
    const float* ea = (const float*)d_in[2];
    const float* W1 = (const float*)d_in[3];
    const float* b1 = (const float*)d_in[4];
    const float* W2 = (const float*)d_in[5];
    const float* b2 = (const float*)d_in[6];
    const float* W3 = (const float*)d_in[7];
    const float* b3 = (const float*)d_in[8];
    float* out = (float*)d_out;

    const int N = N_NODES;
    const int E = N_EDGES;
    const int* src = ei;
    const int* dst = ei + E;

    __half *A, *B, *C;
    int *deg, *indptr, *cursor;
    float2* edges;
    cudaGetSymbolAddress((void**)&A, g_bufA);
    cudaGetSymbolAddress((void**)&B, g_bufB);
    cudaGetSymbolAddress((void**)&C, g_bufC);
    cudaGetSymbolAddress((void**)&deg, g_deg);
    cudaGetSymbolAddress((void**)&indptr, g_indptr);
    cudaGetSymbolAddress((void**)&cursor, g_cursor);
    cudaGetSymbolAddress((void**)&edges, g_edges);

    const int e_blocks    = (E + 255) / 256;
    const int g128_blocks = (N * 32 + 255) / 256;
    const int g64_blocks  = (N * 16 + 255) / 256;
    const int mrows_big   = (N + 127) / 128;   // 391
    const int mrows       = (N + 63) / 64;     // 782

    cudaStream_t s2;
    cudaStreamCreateWithFlags(&s2, cudaStreamNonBlocking);
    cudaEvent_t evFork, evJoin;
    cudaEventCreateWithFlags(&evFork, cudaEventDisableTiming);
    cudaEventCreateWithFlags(&evJoin, cudaEventDisableTiming);

    // --- Fork: CSR build on s2 ∥ GEMM0 on main ---
    cudaEventRecord(evFork, 0);
    cudaStreamWaitEvent(s2, evFork, 0);

    cudaMemsetAsync(deg, 0, N * sizeof(int), s2);
    hist_kernel<<<e_blocks, 256, 0, s2>>>(dst, deg, E);
    scan_kernel<<<1, 1024, 0, s2>>>(deg, indptr, cursor);
    place_kernel<<<e_blocks, 256, 0, s2>>>(src, dst, ea, cursor, edges, E);
    cudaEventRecord(evJoin, s2);

    gemm_big_kernel<0><<<mrows_big, 256>>>(x, W1, A, N);

    cudaStreamWaitEvent(0, evJoin, 0);

    // --- Layer 0: B = x1 = agg(x@W1)+b1 ; C = x1 + relu(x1) ---
    gather128_kernel<0><<<g128_blocks, 256>>>(A, edges, indptr, b1, nullptr, B, C);

    // --- Layer 1: C = x1 + relu(agg(C@W2)+b2) ---
    gemm_big_kernel<1><<<mrows_big, 256>>>(C, W2, A, N);
    gather128_kernel<1><<<g128_blocks, 256>>>(A, edges, indptr, b2, B, C, nullptr);

    // --- Layer 2: out = agg(C@W3)+b3 ---
    gemm_f16_kernel<64, 1><<<dim3(mrows, 1), 128>>>(C, W3, A, N);
    gather64_kernel<<<g64_blocks, 256>>>(A, edges, indptr, b3, out);
}